// round 7
// baseline (speedup 1.0000x reference)
#include <cuda_runtime.h>
#include <cuda_bf16.h>

#define B 512
#define D 768
#define MARGIN 1.0f
#define NBLK 148
#define NTYPES 16

// Scratch (allocation-free rule: __device__ globals)
__device__ float g_gramp[4][B * B];  // K-split partial Gram planes, mirrored
__device__ float g_distp[B * B];     // type-permuted distance matrix
__device__ float g_sqn[B];
__device__ int g_invperm[B];         // j -> permuted position
__device__ int g_off[NTYPES + 1];    // type segment offsets in permuted order
__device__ double g_sum;
__device__ unsigned long long g_count;
__device__ unsigned int g_done;
__device__ unsigned int g_bar;       // zero-init; re-armed by kernel B finisher

union SmemA {
    struct { float As[16][68]; float Bs[16][68]; } gemm;
    float row[B];
};

// ---------------------------------------------------------------------------
// Kernel A (grid = 148 = one wave, 1 CTA/SM):
//  Phase 1: blocks 0..143 Gram (64x64 triangle tiles, 4x4 micro, K-split x4,
//           mirrored plane stores); blocks 144..147 sq-norms; block 147 also
//           builds the type permutation and resets scalars.
//  Grid barrier.
//  Phase 2: all blocks sum planes + sqrt, scatter to permuted rows of g_distp.
// ---------------------------------------------------------------------------
__global__ void gram_dist_kernel(const float* __restrict__ X,
                                 const int* __restrict__ types) {
    __shared__ SmemA sm;
    __shared__ int scnt[NTYPES];
    __shared__ int soff[NTYPES];

    int bid = blockIdx.x;
    int tid = threadIdx.x;
    int lane = tid & 31, warp = tid >> 5;

    // ======================== PHASE 1 ========================
    if (bid >= 144) {
        int rb = (bid - 144) * 128;
        #pragma unroll
        for (int i = 0; i < 16; i++) {
            int row = rb + warp * 16 + i;
            const float4* rp = (const float4*)(X + (size_t)row * D);
            float acc = 0.f;
            #pragma unroll
            for (int q = 0; q < 6; q++) {
                float4 v = rp[lane + 32 * q];
                acc += v.x * v.x + v.y * v.y + v.z * v.z + v.w * v.w;
            }
            #pragma unroll
            for (int o = 16; o; o >>= 1) acc += __shfl_down_sync(0xffffffffu, acc, o);
            if (lane == 0) g_sqn[row] = acc;
        }
        if (bid == 147) {
            // ---- type permutation (single block) ----
            if (tid == 0) { g_sum = 0.0; g_count = 0ull; g_done = 0u; }
            if (tid < NTYPES) scnt[tid] = 0;
            __syncthreads();
            #pragma unroll
            for (int j0 = 0; j0 < B; j0 += 256) {
                atomicAdd(&scnt[types[j0 + tid]], 1);
            }
            __syncthreads();
            if (tid == 0) {
                int run = 0;
                #pragma unroll
                for (int t = 0; t < NTYPES; t++) {
                    soff[t] = run;
                    g_off[t] = run;
                    run += scnt[t];
                }
                g_off[NTYPES] = run;
            }
            __syncthreads();
            #pragma unroll
            for (int j0 = 0; j0 < B; j0 += 256) {
                int j = j0 + tid;
                int pos = atomicAdd(&soff[types[j]], 1);
                g_invperm[j] = pos;
            }
        }
    } else {
        // ---- Gram ----
        int ks = bid & 3;
        int idx = bid >> 2, by = 0;
        for (;;) {
            int len = 8 - by;
            if (idx < len) break;
            idx -= len;
            by++;
        }
        int bx = by + idx;
        int rowBase = by * 64;
        int colBase = bx * 64;

        int tx = tid & 15, ty = tid >> 4;
        int lr = tid & 63;
        int lq = tid >> 6;

        const float* arow = X + (size_t)(rowBase + lr) * D + ks * 192 + lq * 4;
        const float* brow = X + (size_t)(colBase + lr) * D + ks * 192 + lq * 4;

        float acc[4][4];
        #pragma unroll
        for (int i = 0; i < 4; i++)
            #pragma unroll
            for (int j = 0; j < 4; j++) acc[i][j] = 0.f;

        float4 av = *(const float4*)arow;
        float4 bv = *(const float4*)brow;

        for (int kc = 0; kc < 192; kc += 16) {
            sm.gemm.As[lq * 4 + 0][lr] = av.x; sm.gemm.As[lq * 4 + 1][lr] = av.y;
            sm.gemm.As[lq * 4 + 2][lr] = av.z; sm.gemm.As[lq * 4 + 3][lr] = av.w;
            sm.gemm.Bs[lq * 4 + 0][lr] = bv.x; sm.gemm.Bs[lq * 4 + 1][lr] = bv.y;
            sm.gemm.Bs[lq * 4 + 2][lr] = bv.z; sm.gemm.Bs[lq * 4 + 3][lr] = bv.w;
            __syncthreads();
            if (kc + 16 < 192) {
                av = *(const float4*)(arow + kc + 16);
                bv = *(const float4*)(brow + kc + 16);
            }
            #pragma unroll
            for (int k = 0; k < 16; k++) {
                float4 a4 = *(const float4*)&sm.gemm.As[k][ty * 4];
                float4 b4 = *(const float4*)&sm.gemm.Bs[k][tx * 4];
                float a[4] = {a4.x, a4.y, a4.z, a4.w};
                float b[4] = {b4.x, b4.y, b4.z, b4.w};
                #pragma unroll
                for (int i = 0; i < 4; i++)
                    #pragma unroll
                    for (int j = 0; j < 4; j++) acc[i][j] += a[i] * b[j];
            }
            __syncthreads();
        }

        float* plane = g_gramp[ks];
        #pragma unroll
        for (int i = 0; i < 4; i++) {
            int r = rowBase + ty * 4 + i;
            *(float4*)&plane[r * B + colBase + tx * 4] =
                make_float4(acc[i][0], acc[i][1], acc[i][2], acc[i][3]);
        }
        if (bx != by) {
            #pragma unroll
            for (int j = 0; j < 4; j++) {
                int c = colBase + tx * 4 + j;
                *(float4*)&plane[c * B + rowBase + ty * 4] =
                    make_float4(acc[0][j], acc[1][j], acc[2][j], acc[3][j]);
            }
        }
    }

    // ============== grid barrier (148 CTAs, all resident) ==============
    __threadfence();
    __syncthreads();
    if (tid == 0) {
        atomicAdd(&g_bar, 1u);
        volatile unsigned* vb = &g_bar;
        while (*vb < NBLK) { }
    }
    __syncthreads();

    // ======================== PHASE 2: permuted distance rows ==============
    for (int a = bid; a < B; a += NBLK) {
        float sa = g_sqn[a];
        const float* p0 = &g_gramp[0][a * B];
        const float* p1 = &g_gramp[1][a * B];
        const float* p2 = &g_gramp[2][a * B];
        const float* p3 = &g_gramp[3][a * B];
        #pragma unroll
        for (int j0 = 0; j0 < B; j0 += 256) {
            int j = j0 + tid;
            float g = p0[j] + p1[j] + p2[j] + p3[j];
            float dv = (j == a) ? 0.f
                                : sqrtf(fmaxf(sa + g_sqn[j] - 2.f * g, 0.f));
            sm.row[g_invperm[j]] = dv;
        }
        __syncthreads();
        #pragma unroll
        for (int j0 = 0; j0 < B; j0 += 256) {
            g_distp[a * B + j0 + tid] = sm.row[j0 + tid];
        }
        __syncthreads();
    }
}

// ---------------------------------------------------------------------------
// Kernel B: one block per anchor. Load permuted row; positives are the
// contiguous segment [lo,hi); hinge over segment x complement; last block
// finalizes and re-arms the barrier.
// ---------------------------------------------------------------------------
__global__ void triplet_kernel(const int* __restrict__ types,
                               float* __restrict__ out) {
    int a = blockIdx.x;
    __shared__ float row[B];
    __shared__ float ws[8];
    int tid = threadIdx.x;
    int lane = tid & 31, warp = tid >> 5;

    #pragma unroll
    for (int j0 = 0; j0 < B; j0 += 256)
        row[j0 + tid] = g_distp[a * B + j0 + tid];
    __syncthreads();

    int t = types[a];
    int lo = g_off[t], hi = g_off[t + 1];
    int np = hi - lo, nn = B - np;
    int seg = hi - lo;

    float acc = 0.f;
    for (int p = lo + warp; p < hi; p += 8) {
        float dp = row[p] + MARGIN;
        for (int m = lane; m < nn; m += 32) {
            int j = (m < lo) ? m : m + seg;
            acc += fmaxf(dp - row[j], 0.f);
        }
    }

    #pragma unroll
    for (int o = 16; o; o >>= 1) acc += __shfl_down_sync(0xffffffffu, acc, o);
    if (lane == 0) ws[warp] = acc;
    __syncthreads();
    if (tid == 0) {
        float s = 0.f;
        #pragma unroll
        for (int w = 0; w < 8; w++) s += ws[w];
        atomicAdd(&g_sum, (double)s);
        atomicAdd(&g_count, (unsigned long long)((long long)np * nn));
        __threadfence();
        unsigned d = atomicInc(&g_done, 0xffffffffu);
        if (d == B - 1) {
            double S = atomicAdd(&g_sum, 0.0);
            unsigned long long C = atomicAdd(&g_count, 0ull);
            double V = (double)C;
            double b3 = 134217728.0;  // 512^3
            out[0] = (float)(((b3 - V) * (double)MARGIN + S) / V);
            __threadfence();
            g_bar = 0u;  // re-arm kernel A's barrier for the next replay
        }
    }
}

extern "C" void kernel_launch(void* const* d_in, const int* in_sizes, int n_in,
                              void* d_out, int out_size) {
    int ti = 0, ei = 1;
    if (in_sizes[0] == B * D) { ti = 1; ei = 0; }
    const int* types = (const int*)d_in[ti];
    const float* X = (const float*)d_in[ei];
    float* out = (float*)d_out;

    gram_dist_kernel<<<NBLK, 256>>>(X, types);
    triplet_kernel<<<B, 256>>>(types, out);
}

// round 8
// speedup vs baseline: 1.0387x; 1.0387x over previous
#include <cuda_runtime.h>
#include <cuda_bf16.h>

#define B 512
#define D 768
#define MARGIN 1.0f
#define NTYPES 16

// Scratch (allocation-free rule: __device__ globals)
__device__ float g_gramp[4][B * B];  // type-permuted K-split Gram planes, mirrored
__device__ float g_sqn[B];           // sq-norms in permuted order
__device__ int g_off[NTYPES + 1];    // type segment offsets
__device__ double g_sum;
__device__ unsigned int g_done;

// ---------------------------------------------------------------------------
// Deterministic type-sort permutation, built identically by every block.
// sperm[p] = original index of permuted position p.
// ---------------------------------------------------------------------------
__device__ __forceinline__ void build_perm(const int* __restrict__ types,
                                           int* sperm, int* scnt, int* srun,
                                           int* sofs, int tid, int lane, int warp) {
    unsigned lt = (1u << lane) - 1u;
    if (tid < NTYPES) { scnt[tid] = 0; srun[tid] = 0; }
    __syncthreads();
    if (warp == 0) {
        #pragma unroll
        for (int c = 0; c < B / 32; c++) {
            int t = types[c * 32 + lane];
            unsigned m = __match_any_sync(0xffffffffu, t);
            if ((__ffs(m) - 1) == lane) scnt[t] += __popc(m);
            __syncwarp();
        }
    }
    __syncthreads();
    if (tid == 0) {
        int run = 0;
        #pragma unroll
        for (int t = 0; t < NTYPES; t++) { sofs[t] = run; run += scnt[t]; }
        sofs[NTYPES] = run;
    }
    __syncthreads();
    if (warp == 0) {
        #pragma unroll
        for (int c = 0; c < B / 32; c++) {
            int j = c * 32 + lane;
            int t = types[j];
            unsigned m = __match_any_sync(0xffffffffu, t);
            int rank = srun[t] + __popc(m & lt);
            sperm[sofs[t] + rank] = j;
            __syncwarp();
            if ((__ffs(m) - 1) == lane) srun[t] += __popc(m);
            __syncwarp();
        }
    }
    __syncthreads();
}

// ---------------------------------------------------------------------------
// Kernel A: 148 blocks (one wave).
//   blocks 0..143  : type-permuted Gram, 64x64 triangle tiles, 4x4 micro-tile,
//                    K-split x4, pipelined loads, mirrored plane stores
//   blocks 144..147: permuted sq-norms (128 rows each); block 147 writes g_off
// ---------------------------------------------------------------------------
__global__ void __launch_bounds__(256)
gram_sqnorm_kernel(const float* __restrict__ X, const int* __restrict__ types) {
    __shared__ float As[16][68];
    __shared__ float Bs[16][68];
    __shared__ int sperm[B];
    __shared__ int scnt[NTYPES], srun[NTYPES], sofs[NTYPES + 1];

    int bid = blockIdx.x;
    int tid = threadIdx.x;
    int lane = tid & 31, warp = tid >> 5;

    build_perm(types, sperm, scnt, srun, sofs, tid, lane, warp);

    if (bid >= 144) {
        // ---- permuted sq-norms ----
        if (bid == 147 && tid <= NTYPES) g_off[tid] = sofs[tid];
        int rb = (bid - 144) * 128;
        #pragma unroll
        for (int i = 0; i < 16; i++) {
            int pr = rb + warp * 16 + i;
            const float4* rp = (const float4*)(X + (size_t)sperm[pr] * D);
            float acc = 0.f;
            #pragma unroll
            for (int q = 0; q < 6; q++) {
                float4 v = rp[lane + 32 * q];
                acc += v.x * v.x + v.y * v.y + v.z * v.z + v.w * v.w;
            }
            #pragma unroll
            for (int o = 16; o; o >>= 1) acc += __shfl_down_sync(0xffffffffu, acc, o);
            if (lane == 0) g_sqn[pr] = acc;
        }
        return;
    }

    // ---- permuted Gram ----
    int ks = bid & 3;            // k-slice 0..3
    int idx = bid >> 2, by = 0;  // tile 0..35 -> (by, bx), bx >= by, 8x8 grid
    for (;;) {
        int len = 8 - by;
        if (idx < len) break;
        idx -= len;
        by++;
    }
    int bx = by + idx;
    int rowBase = by * 64;
    int colBase = bx * 64;

    int tx = tid & 15, ty = tid >> 4;
    int lr = tid & 63;
    int lq = tid >> 6;

    // rows gathered through the permutation; each row read stays coalesced
    const float* arow = X + (size_t)sperm[rowBase + lr] * D + ks * 192 + lq * 4;
    const float* brow = X + (size_t)sperm[colBase + lr] * D + ks * 192 + lq * 4;

    float acc[4][4];
    #pragma unroll
    for (int i = 0; i < 4; i++)
        #pragma unroll
        for (int j = 0; j < 4; j++) acc[i][j] = 0.f;

    float4 av = *(const float4*)arow;
    float4 bv = *(const float4*)brow;

    for (int kc = 0; kc < 192; kc += 16) {
        As[lq * 4 + 0][lr] = av.x; As[lq * 4 + 1][lr] = av.y;
        As[lq * 4 + 2][lr] = av.z; As[lq * 4 + 3][lr] = av.w;
        Bs[lq * 4 + 0][lr] = bv.x; Bs[lq * 4 + 1][lr] = bv.y;
        Bs[lq * 4 + 2][lr] = bv.z; Bs[lq * 4 + 3][lr] = bv.w;
        __syncthreads();
        if (kc + 16 < 192) {
            av = *(const float4*)(arow + kc + 16);
            bv = *(const float4*)(brow + kc + 16);
        }
        #pragma unroll
        for (int k = 0; k < 16; k++) {
            float4 a4 = *(const float4*)&As[k][ty * 4];
            float4 b4 = *(const float4*)&Bs[k][tx * 4];
            float a[4] = {a4.x, a4.y, a4.z, a4.w};
            float b[4] = {b4.x, b4.y, b4.z, b4.w};
            #pragma unroll
            for (int i = 0; i < 4; i++)
                #pragma unroll
                for (int j = 0; j < 4; j++) acc[i][j] += a[i] * b[j];
        }
        __syncthreads();
    }

    float* plane = g_gramp[ks];
    #pragma unroll
    for (int i = 0; i < 4; i++) {
        int r = rowBase + ty * 4 + i;
        *(float4*)&plane[r * B + colBase + tx * 4] =
            make_float4(acc[i][0], acc[i][1], acc[i][2], acc[i][3]);
    }
    if (bx != by) {
        #pragma unroll
        for (int j = 0; j < 4; j++) {
            int c = colBase + tx * 4 + j;
            *(float4*)&plane[c * B + rowBase + ty * 4] =
                make_float4(acc[0][j], acc[1][j], acc[2][j], acc[3][j]);
        }
    }
}

// ---------------------------------------------------------------------------
// Kernel B: grid = 2*B = 1024 blocks: (anchor, side). Positives are the
// contiguous segment [lo,hi); side 0 hinges against negatives [0,lo),
// side 1 against [hi,B). Columns needed are one contiguous range either way.
// Distances computed on the fly from the permuted planes (coalesced rows).
// ---------------------------------------------------------------------------
__global__ void __launch_bounds__(256)
triplet_kernel(float* __restrict__ out) {
    __shared__ float row[B];
    __shared__ float ws[8];
    __shared__ int soff[NTYPES + 1];
    int bid = blockIdx.x;
    int tid = threadIdx.x;
    int lane = tid & 31, warp = tid >> 5;
    int a = bid >> 1, side = bid & 1;

    if (tid <= NTYPES) soff[tid] = g_off[tid];
    __syncthreads();

    int t = 0;
    #pragma unroll
    for (int i = 1; i < NTYPES; i++)
        if (a >= soff[i]) t = i;
    int lo = soff[t], hi = soff[t + 1];

    // columns to materialize: segment + this side's negatives (contiguous)
    int cs = side ? lo : 0;
    int ce = side ? B : hi;

    float sa = g_sqn[a];
    const float* p0 = &g_gramp[0][a * B];
    const float* p1 = &g_gramp[1][a * B];
    const float* p2 = &g_gramp[2][a * B];
    const float* p3 = &g_gramp[3][a * B];
    for (int j = cs + tid; j < ce; j += 256) {
        float g = p0[j] + p1[j] + p2[j] + p3[j];
        row[j] = (j == a) ? 0.f
                          : sqrtf(fmaxf(sa + g_sqn[j] - 2.f * g, 0.f));
    }
    __syncthreads();

    int ns = side ? hi : 0;
    int ne = side ? B : lo;
    float acc = 0.f;
    for (int p = lo + warp; p < hi; p += 8) {
        float dpm = row[p] + MARGIN;
        for (int n = ns + lane; n < ne; n += 32)
            acc += fmaxf(dpm - row[n], 0.f);
    }

    #pragma unroll
    for (int o = 16; o; o >>= 1) acc += __shfl_down_sync(0xffffffffu, acc, o);
    if (lane == 0) ws[warp] = acc;
    __syncthreads();
    if (tid == 0) {
        float s = 0.f;
        #pragma unroll
        for (int w = 0; w < 8; w++) s += ws[w];
        atomicAdd(&g_sum, (double)s);
        __threadfence();
        unsigned d = atomicInc(&g_done, 0xffffffffu);
        if (d == 2 * B - 1) {
            double S = atomicAdd(&g_sum, 0.0);
            double V = 0.0;
            #pragma unroll
            for (int tt = 0; tt < NTYPES; tt++) {
                double c = (double)(soff[tt + 1] - soff[tt]);
                V += c * c * ((double)B - c);
            }
            double b3 = 134217728.0;  // 512^3
            out[0] = (float)(((b3 - V) * (double)MARGIN + S) / V);
            // reset scalars for the next graph replay
            g_sum = 0.0;
            g_done = 0u;
        }
    }
}

extern "C" void kernel_launch(void* const* d_in, const int* in_sizes, int n_in,
                              void* d_out, int out_size) {
    int ti = 0, ei = 1;
    if (in_sizes[0] == B * D) { ti = 1; ei = 0; }
    const int* types = (const int*)d_in[ti];
    const float* X = (const float*)d_in[ei];
    float* out = (float*)d_out;

    gram_sqnorm_kernel<<<148, 256>>>(X, types);
    triplet_kernel<<<2 * B, 256>>>(out);
}

// round 9
// speedup vs baseline: 1.0710x; 1.0310x over previous
#include <cuda_runtime.h>
#include <cuda_bf16.h>

#define B 512
#define D 768
#define MARGIN 1.0f
#define WPA 4      // warps per anchor in kernel B
#define PMAX 128   // max positives per anchor supported

// Scratch (allocation-free rule: __device__ globals)
__device__ float g_gramp[4][B * B];  // K-split partial Gram planes, mirrored
__device__ float g_sqn[B];
__device__ double g_sum;
__device__ unsigned long long g_count;
__device__ unsigned int g_done;

// ---------------------------------------------------------------------------
// Kernel A (= round-6 proven version): one wave of 148 blocks.
//   blocks 0..143  : upper-triangle Gram, 64x64 tiles, 4x4 micro-tile,
//                    K-split x4, pipelined global loads, mirrored plane stores
//   blocks 144..147: sq-norms (128 rows each); block 147 resets scalars
// ---------------------------------------------------------------------------
__global__ void gram_sqnorm_kernel(const float* __restrict__ X) {
    __shared__ float As[16][68];  // [k][row], padded
    __shared__ float Bs[16][68];

    int bid = blockIdx.x;
    int tid = threadIdx.x;
    int lane = tid & 31, warp = tid >> 5;

    if (bid >= 144) {
        if (bid == 147 && tid == 0) {
            g_sum = 0.0;
            g_count = 0ull;
            g_done = 0u;
        }
        int rb = (bid - 144) * 128;
        #pragma unroll
        for (int i = 0; i < 16; i++) {
            int row = rb + warp * 16 + i;
            const float4* rp = (const float4*)(X + (size_t)row * D);
            float acc = 0.f;
            #pragma unroll
            for (int q = 0; q < 6; q++) {
                float4 v = rp[lane + 32 * q];
                acc += v.x * v.x + v.y * v.y + v.z * v.z + v.w * v.w;
            }
            #pragma unroll
            for (int o = 16; o; o >>= 1) acc += __shfl_down_sync(0xffffffffu, acc, o);
            if (lane == 0) g_sqn[row] = acc;
        }
        return;
    }

    int ks = bid & 3;            // k-slice 0..3
    int idx = bid >> 2, by = 0;  // tile 0..35 -> (by, bx), bx >= by, 8x8 grid
    for (;;) {
        int len = 8 - by;
        if (idx < len) break;
        idx -= len;
        by++;
    }
    int bx = by + idx;
    int rowBase = by * 64;
    int colBase = bx * 64;

    int tx = tid & 15, ty = tid >> 4;
    int lr = tid & 63;
    int lq = tid >> 6;

    const float* arow = X + (size_t)(rowBase + lr) * D + ks * 192 + lq * 4;
    const float* brow = X + (size_t)(colBase + lr) * D + ks * 192 + lq * 4;

    float acc[4][4];
    #pragma unroll
    for (int i = 0; i < 4; i++)
        #pragma unroll
        for (int j = 0; j < 4; j++) acc[i][j] = 0.f;

    float4 av = *(const float4*)arow;
    float4 bv = *(const float4*)brow;

    for (int kc = 0; kc < 192; kc += 16) {
        As[lq * 4 + 0][lr] = av.x; As[lq * 4 + 1][lr] = av.y;
        As[lq * 4 + 2][lr] = av.z; As[lq * 4 + 3][lr] = av.w;
        Bs[lq * 4 + 0][lr] = bv.x; Bs[lq * 4 + 1][lr] = bv.y;
        Bs[lq * 4 + 2][lr] = bv.z; Bs[lq * 4 + 3][lr] = bv.w;
        __syncthreads();
        if (kc + 16 < 192) {
            av = *(const float4*)(arow + kc + 16);
            bv = *(const float4*)(brow + kc + 16);
        }
        #pragma unroll
        for (int k = 0; k < 16; k++) {
            float4 a4 = *(const float4*)&As[k][ty * 4];
            float4 b4 = *(const float4*)&Bs[k][tx * 4];
            float a[4] = {a4.x, a4.y, a4.z, a4.w};
            float b[4] = {b4.x, b4.y, b4.z, b4.w};
            #pragma unroll
            for (int i = 0; i < 4; i++)
                #pragma unroll
                for (int j = 0; j < 4; j++) acc[i][j] += a[i] * b[j];
        }
        __syncthreads();
    }

    float* plane = g_gramp[ks];
    #pragma unroll
    for (int i = 0; i < 4; i++) {
        int r = rowBase + ty * 4 + i;
        *(float4*)&plane[r * B + colBase + tx * 4] =
            make_float4(acc[i][0], acc[i][1], acc[i][2], acc[i][3]);
    }
    if (bx != by) {
        #pragma unroll
        for (int j = 0; j < 4; j++) {
            int c = colBase + tx * 4 + j;
            *(float4*)&plane[c * B + rowBase + ty * 4] =
                make_float4(acc[0][j], acc[1][j], acc[2][j], acc[3][j]);
        }
    }
}

// ---------------------------------------------------------------------------
// Kernel B: warp-per-anchor-slice. grid = B*WPA/8 blocks x 256 threads.
// Each warp: finds its anchor's positives by ballot scan (smem type table),
// computes their distances itself into warp-private smem (no block sync),
// then hinges its WPA-strided 32-column chunks with invalid lanes masked to
// +BIG. One RED.F64 per warp; last warp finalizes.
// ---------------------------------------------------------------------------
__global__ void __launch_bounds__(256)
triplet_kernel(const int* __restrict__ types, float* __restrict__ out) {
    __shared__ int stype[B];
    __shared__ float ssqn[B];
    __shared__ float posw[8][PMAX];

    int tid = threadIdx.x;
    int lane = tid & 31, warp = tid >> 5;

    #pragma unroll
    for (int j0 = 0; j0 < B; j0 += 256) {
        stype[j0 + tid] = types[j0 + tid];
        ssqn[j0 + tid] = g_sqn[j0 + tid];
    }
    __syncthreads();  // only block-wide sync in the kernel

    int gw = blockIdx.x * 8 + warp;
    int a = gw / WPA;
    int part = gw & (WPA - 1);
    int ta = stype[a];
    float sa = ssqn[a];

    const float* p0 = &g_gramp[0][a * B];
    const float* p1 = &g_gramp[1][a * B];
    const float* p2 = &g_gramp[2][a * B];
    const float* p3 = &g_gramp[3][a * B];

    // ---- pass 1: gather positives (dp + MARGIN) into warp-private smem ----
    unsigned lt = (1u << lane) - 1u;
    int np = 0;
    #pragma unroll
    for (int c = 0; c < B / 32; c++) {
        int j = c * 32 + lane;
        bool isPos = (stype[j] == ta);
        unsigned m = __ballot_sync(0xffffffffu, isPos);
        if (isPos) {
            float g = p0[j] + p1[j] + p2[j] + p3[j];
            float dp = (j == a) ? 0.f
                                : sqrtf(fmaxf(sa + ssqn[j] - 2.f * g, 0.f));
            posw[warp][np + __popc(m & lt)] = dp + MARGIN;
        }
        np += __popc(m);
    }
    __syncwarp();

    // ---- pass 2: hinge over this warp's negative chunks ----
    float acc0 = 0.f, acc1 = 0.f;
    #pragma unroll
    for (int ci = 0; ci < B / 32 / WPA; ci++) {
        int j = (part + ci * WPA) * 32 + lane;
        bool isNeg = (stype[j] != ta);
        float g = p0[j] + p1[j] + p2[j] + p3[j];
        float dn = isNeg ? sqrtf(fmaxf(sa + ssqn[j] - 2.f * g, 0.f)) : 1e30f;
        int p = 0;
        for (; p + 2 <= np; p += 2) {
            acc0 += fmaxf(posw[warp][p]     - dn, 0.f);
            acc1 += fmaxf(posw[warp][p + 1] - dn, 0.f);
        }
        if (p < np) acc0 += fmaxf(posw[warp][p] - dn, 0.f);
    }
    float acc = acc0 + acc1;

    #pragma unroll
    for (int o = 16; o; o >>= 1) acc += __shfl_down_sync(0xffffffffu, acc, o);

    if (lane == 0) {
        atomicAdd(&g_sum, (double)acc);
        if (part == 0)
            atomicAdd(&g_count, (unsigned long long)np * (unsigned)(B - np));
        __threadfence();
        unsigned d = atomicInc(&g_done, 0xffffffffu);
        if (d == (unsigned)(B * WPA) - 1u) {
            double S = atomicAdd(&g_sum, 0.0);
            unsigned long long C = atomicAdd(&g_count, 0ull);
            double V = (double)C;
            double b3 = 134217728.0;  // 512^3
            out[0] = (float)(((b3 - V) * (double)MARGIN + S) / V);
        }
    }
}

extern "C" void kernel_launch(void* const* d_in, const int* in_sizes, int n_in,
                              void* d_out, int out_size) {
    int ti = 0, ei = 1;
    if (in_sizes[0] == B * D) { ti = 1; ei = 0; }
    const int* types = (const int*)d_in[ti];
    const float* X = (const float*)d_in[ei];
    float* out = (float*)d_out;

    gram_sqnorm_kernel<<<148, 256>>>(X);
    triplet_kernel<<<B * WPA / 8, 256>>>(types, out);
}

// round 10
// speedup vs baseline: 1.4659x; 1.3687x over previous
#include <cuda_runtime.h>
#include <cuda_bf16.h>

#define B 512
#define D 768
#define MARGIN 1.0f

// Scratch (allocation-free rule: __device__ globals)
__device__ float g_gramp[4][B * B];  // K-split partial Gram planes, mirrored
__device__ float g_sqn[B];
__device__ double g_sum;
__device__ unsigned long long g_count;
__device__ unsigned int g_done;

// ---------------------------------------------------------------------------
// Kernel A (round-6 proven version, unchanged): one wave of 148 blocks.
//   blocks 0..143  : upper-triangle Gram, 64x64 tiles, 4x4 micro-tile,
//                    K-split x4, pipelined global loads, mirrored plane stores
//   blocks 144..147: sq-norms (128 rows each); block 147 resets scalars
// ---------------------------------------------------------------------------
__global__ void gram_sqnorm_kernel(const float* __restrict__ X) {
    __shared__ float As[16][68];  // [k][row], padded
    __shared__ float Bs[16][68];

    int bid = blockIdx.x;
    int tid = threadIdx.x;
    int lane = tid & 31, warp = tid >> 5;

    if (bid >= 144) {
        if (bid == 147 && tid == 0) {
            g_sum = 0.0;
            g_count = 0ull;
            g_done = 0u;
        }
        int rb = (bid - 144) * 128;
        #pragma unroll
        for (int i = 0; i < 16; i++) {
            int row = rb + warp * 16 + i;
            const float4* rp = (const float4*)(X + (size_t)row * D);
            float acc = 0.f;
            #pragma unroll
            for (int q = 0; q < 6; q++) {
                float4 v = rp[lane + 32 * q];
                acc += v.x * v.x + v.y * v.y + v.z * v.z + v.w * v.w;
            }
            #pragma unroll
            for (int o = 16; o; o >>= 1) acc += __shfl_down_sync(0xffffffffu, acc, o);
            if (lane == 0) g_sqn[row] = acc;
        }
        return;
    }

    int ks = bid & 3;            // k-slice 0..3
    int idx = bid >> 2, by = 0;  // tile 0..35 -> (by, bx), bx >= by, 8x8 grid
    for (;;) {
        int len = 8 - by;
        if (idx < len) break;
        idx -= len;
        by++;
    }
    int bx = by + idx;
    int rowBase = by * 64;
    int colBase = bx * 64;

    int tx = tid & 15, ty = tid >> 4;
    int lr = tid & 63;
    int lq = tid >> 6;

    const float* arow = X + (size_t)(rowBase + lr) * D + ks * 192 + lq * 4;
    const float* brow = X + (size_t)(colBase + lr) * D + ks * 192 + lq * 4;

    float acc[4][4];
    #pragma unroll
    for (int i = 0; i < 4; i++)
        #pragma unroll
        for (int j = 0; j < 4; j++) acc[i][j] = 0.f;

    float4 av = *(const float4*)arow;
    float4 bv = *(const float4*)brow;

    for (int kc = 0; kc < 192; kc += 16) {
        As[lq * 4 + 0][lr] = av.x; As[lq * 4 + 1][lr] = av.y;
        As[lq * 4 + 2][lr] = av.z; As[lq * 4 + 3][lr] = av.w;
        Bs[lq * 4 + 0][lr] = bv.x; Bs[lq * 4 + 1][lr] = bv.y;
        Bs[lq * 4 + 2][lr] = bv.z; Bs[lq * 4 + 3][lr] = bv.w;
        __syncthreads();
        if (kc + 16 < 192) {
            av = *(const float4*)(arow + kc + 16);
            bv = *(const float4*)(brow + kc + 16);
        }
        #pragma unroll
        for (int k = 0; k < 16; k++) {
            float4 a4 = *(const float4*)&As[k][ty * 4];
            float4 b4 = *(const float4*)&Bs[k][tx * 4];
            float a[4] = {a4.x, a4.y, a4.z, a4.w};
            float b[4] = {b4.x, b4.y, b4.z, b4.w};
            #pragma unroll
            for (int i = 0; i < 4; i++)
                #pragma unroll
                for (int j = 0; j < 4; j++) acc[i][j] += a[i] * b[j];
        }
        __syncthreads();
    }

    float* plane = g_gramp[ks];
    #pragma unroll
    for (int i = 0; i < 4; i++) {
        int r = rowBase + ty * 4 + i;
        *(float4*)&plane[r * B + colBase + tx * 4] =
            make_float4(acc[i][0], acc[i][1], acc[i][2], acc[i][3]);
    }
    if (bx != by) {
        #pragma unroll
        for (int j = 0; j < 4; j++) {
            int c = colBase + tx * 4 + j;
            *(float4*)&plane[c * B + rowBase + ty * 4] =
                make_float4(acc[0][j], acc[1][j], acc[2][j], acc[3][j]);
        }
    }
}

// ---------------------------------------------------------------------------
// Kernel B (R6 structure + 4-positives-per-iteration hinge):
// one block per anchor; coalesced 4-plane row reads; ballot compaction;
// hinge loop holds 4 positives in registers per LDS.128 of negatives
// (32 flops per 16B shared load, 4 independent accumulation streams).
// Last block finalizes.
// ---------------------------------------------------------------------------
__global__ void triplet_kernel(const int* __restrict__ types,
                               float* __restrict__ out) {
    int a = blockIdx.x;
    __shared__ __align__(16) float posv[B + 4];
    __shared__ __align__(16) float negv[B + 4];
    __shared__ int cnt[2];
    __shared__ float ws[8];
    int tid = threadIdx.x;
    int lane = tid & 31, warp = tid >> 5;
    if (tid < 2) cnt[tid] = 0;
    __syncthreads();

    int ta = types[a];
    float sa = g_sqn[a];
    const float* p0 = &g_gramp[0][a * B];
    const float* p1 = &g_gramp[1][a * B];
    const float* p2 = &g_gramp[2][a * B];
    const float* p3 = &g_gramp[3][a * B];
    unsigned lt_mask = (1u << lane) - 1u;

    #pragma unroll
    for (int j0 = 0; j0 < B; j0 += 256) {
        int j = j0 + tid;
        float g = p0[j] + p1[j] + p2[j] + p3[j];
        float dv = (j == a) ? 0.f
                            : sqrtf(fmaxf(sa + g_sqn[j] - 2.f * g, 0.f));
        bool isPos = (types[j] == ta);
        unsigned mp = __ballot_sync(0xffffffffu, isPos);
        int cp = __popc(mp);
        int bp = 0, bn = 0;
        if (lane == 0) {
            bp = atomicAdd(&cnt[0], cp);
            bn = atomicAdd(&cnt[1], 32 - cp);
        }
        bp = __shfl_sync(0xffffffffu, bp, 0);
        bn = __shfl_sync(0xffffffffu, bn, 0);
        if (isPos) posv[bp + __popc(mp & lt_mask)] = dv;
        else       negv[bn + __popc((~mp) & lt_mask)] = dv;
    }
    __syncthreads();

    int np = cnt[0], nn = cnt[1];
    int nn4 = (nn + 3) & ~3;
    int np4 = (np + 3) & ~3;
    if (tid < nn4 - nn) negv[nn + tid] = 1e30f;   // pad: max(dp - INF, 0) = 0
    if (tid < np4 - np) posv[np + tid] = -1e30f;  // pad: max(-INF - dn, 0) = 0
    __syncthreads();

    const float4* negv4 = (const float4*)negv;
    int nq = nn4 >> 2;
    float a0 = 0.f, a1 = 0.f, a2 = 0.f, a3 = 0.f;
    for (int p = warp * 4; p < np4; p += 32) {  // 8 warps x 4 positives each
        float dp0 = posv[p + 0] + MARGIN;
        float dp1 = posv[p + 1] + MARGIN;
        float dp2 = posv[p + 2] + MARGIN;
        float dp3 = posv[p + 3] + MARGIN;
        for (int n = lane; n < nq; n += 32) {
            float4 v = negv4[n];
            a0 += fmaxf(dp0 - v.x, 0.f); a0 += fmaxf(dp0 - v.y, 0.f);
            a0 += fmaxf(dp0 - v.z, 0.f); a0 += fmaxf(dp0 - v.w, 0.f);
            a1 += fmaxf(dp1 - v.x, 0.f); a1 += fmaxf(dp1 - v.y, 0.f);
            a1 += fmaxf(dp1 - v.z, 0.f); a1 += fmaxf(dp1 - v.w, 0.f);
            a2 += fmaxf(dp2 - v.x, 0.f); a2 += fmaxf(dp2 - v.y, 0.f);
            a2 += fmaxf(dp2 - v.z, 0.f); a2 += fmaxf(dp2 - v.w, 0.f);
            a3 += fmaxf(dp3 - v.x, 0.f); a3 += fmaxf(dp3 - v.y, 0.f);
            a3 += fmaxf(dp3 - v.z, 0.f); a3 += fmaxf(dp3 - v.w, 0.f);
        }
    }
    float acc = (a0 + a1) + (a2 + a3);

    #pragma unroll
    for (int o = 16; o; o >>= 1) acc += __shfl_down_sync(0xffffffffu, acc, o);
    if (lane == 0) ws[warp] = acc;
    __syncthreads();
    if (tid == 0) {
        float s = 0.f;
        #pragma unroll
        for (int w = 0; w < 8; w++) s += ws[w];
        atomicAdd(&g_sum, (double)s);
        atomicAdd(&g_count, (unsigned long long)((long long)np * nn));
        __threadfence();
        unsigned d = atomicInc(&g_done, 0xffffffffu);
        if (d == B - 1) {
            double S = atomicAdd(&g_sum, 0.0);
            unsigned long long C = atomicAdd(&g_count, 0ull);
            double V = (double)C;
            double b3 = 134217728.0;  // 512^3
            out[0] = (float)(((b3 - V) * (double)MARGIN + S) / V);
        }
    }
}

extern "C" void kernel_launch(void* const* d_in, const int* in_sizes, int n_in,
                              void* d_out, int out_size) {
    int ti = 0, ei = 1;
    if (in_sizes[0] == B * D) { ti = 1; ei = 0; }
    const int* types = (const int*)d_in[ti];
    const float* X = (const float*)d_in[ei];
    float* out = (float*)d_out;

    gram_sqnorm_kernel<<<148, 256>>>(X);
    triplet_kernel<<<B, 256>>>(types, out);
}

// round 11
// speedup vs baseline: 1.4748x; 1.0061x over previous
#include <cuda_runtime.h>
#include <cuda_bf16.h>

#define B 512
#define D 768
#define MARGIN 1.0f

// Scratch (allocation-free rule: __device__ globals)
__device__ float g_gramp[4][B * B];  // K-split partial Gram planes, mirrored
__device__ float g_sqn[B];
__device__ double g_sum;
__device__ unsigned long long g_count;
__device__ unsigned int g_done;

// ---------------------------------------------------------------------------
// Kernel A (round-6 proven version, unchanged): one wave of 148 blocks.
//   blocks 0..143  : upper-triangle Gram, 64x64 tiles, 4x4 micro-tile,
//                    K-split x4, pipelined global loads, mirrored plane stores
//   blocks 144..147: sq-norms (128 rows each); block 147 resets scalars
// ---------------------------------------------------------------------------
__global__ void gram_sqnorm_kernel(const float* __restrict__ X) {
    __shared__ float As[16][68];  // [k][row], padded
    __shared__ float Bs[16][68];

    int bid = blockIdx.x;
    int tid = threadIdx.x;
    int lane = tid & 31, warp = tid >> 5;

    if (bid >= 144) {
        if (bid == 147 && tid == 0) {
            g_sum = 0.0;
            g_count = 0ull;
            g_done = 0u;
        }
        int rb = (bid - 144) * 128;
        #pragma unroll
        for (int i = 0; i < 16; i++) {
            int row = rb + warp * 16 + i;
            const float4* rp = (const float4*)(X + (size_t)row * D);
            float acc = 0.f;
            #pragma unroll
            for (int q = 0; q < 6; q++) {
                float4 v = rp[lane + 32 * q];
                acc += v.x * v.x + v.y * v.y + v.z * v.z + v.w * v.w;
            }
            #pragma unroll
            for (int o = 16; o; o >>= 1) acc += __shfl_down_sync(0xffffffffu, acc, o);
            if (lane == 0) g_sqn[row] = acc;
        }
        return;
    }

    int ks = bid & 3;            // k-slice 0..3
    int idx = bid >> 2, by = 0;  // tile 0..35 -> (by, bx), bx >= by, 8x8 grid
    for (;;) {
        int len = 8 - by;
        if (idx < len) break;
        idx -= len;
        by++;
    }
    int bx = by + idx;
    int rowBase = by * 64;
    int colBase = bx * 64;

    int tx = tid & 15, ty = tid >> 4;
    int lr = tid & 63;
    int lq = tid >> 6;

    const float* arow = X + (size_t)(rowBase + lr) * D + ks * 192 + lq * 4;
    const float* brow = X + (size_t)(colBase + lr) * D + ks * 192 + lq * 4;

    float acc[4][4];
    #pragma unroll
    for (int i = 0; i < 4; i++)
        #pragma unroll
        for (int j = 0; j < 4; j++) acc[i][j] = 0.f;

    float4 av = *(const float4*)arow;
    float4 bv = *(const float4*)brow;

    for (int kc = 0; kc < 192; kc += 16) {
        As[lq * 4 + 0][lr] = av.x; As[lq * 4 + 1][lr] = av.y;
        As[lq * 4 + 2][lr] = av.z; As[lq * 4 + 3][lr] = av.w;
        Bs[lq * 4 + 0][lr] = bv.x; Bs[lq * 4 + 1][lr] = bv.y;
        Bs[lq * 4 + 2][lr] = bv.z; Bs[lq * 4 + 3][lr] = bv.w;
        __syncthreads();
        if (kc + 16 < 192) {
            av = *(const float4*)(arow + kc + 16);
            bv = *(const float4*)(brow + kc + 16);
        }
        #pragma unroll
        for (int k = 0; k < 16; k++) {
            float4 a4 = *(const float4*)&As[k][ty * 4];
            float4 b4 = *(const float4*)&Bs[k][tx * 4];
            float a[4] = {a4.x, a4.y, a4.z, a4.w};
            float b[4] = {b4.x, b4.y, b4.z, b4.w};
            #pragma unroll
            for (int i = 0; i < 4; i++)
                #pragma unroll
                for (int j = 0; j < 4; j++) acc[i][j] += a[i] * b[j];
        }
        __syncthreads();
    }

    float* plane = g_gramp[ks];
    #pragma unroll
    for (int i = 0; i < 4; i++) {
        int r = rowBase + ty * 4 + i;
        *(float4*)&plane[r * B + colBase + tx * 4] =
            make_float4(acc[i][0], acc[i][1], acc[i][2], acc[i][3]);
    }
    if (bx != by) {
        #pragma unroll
        for (int j = 0; j < 4; j++) {
            int c = colBase + tx * 4 + j;
            *(float4*)&plane[c * B + rowBase + ty * 4] =
                make_float4(acc[0][j], acc[1][j], acc[2][j], acc[3][j]);
        }
    }
}

// ---------------------------------------------------------------------------
// Kernel B: one block per anchor. Prologue fully hoisted: each thread owns
// j = {2*tid, 2*tid+1} and issues 6 wide loads (4x float2 plane, float2 sqn,
// int2 types) back-to-back before any dependent compute -> single latency
// window, high MLP. Two independent ballot-compaction passes (order of
// posv/negv is irrelevant to the sum). Hinge: 4 positives in registers per
// LDS.128 of negatives. Last block finalizes.
// ---------------------------------------------------------------------------
__global__ void __launch_bounds__(256)
triplet_kernel(const int* __restrict__ types, float* __restrict__ out) {
    int a = blockIdx.x;
    __shared__ __align__(16) float posv[B + 4];
    __shared__ __align__(16) float negv[B + 4];
    __shared__ int cnt[2];
    __shared__ float ws[8];
    int tid = threadIdx.x;
    int lane = tid & 31, warp = tid >> 5;
    if (tid < 2) cnt[tid] = 0;

    // ---- hoisted loads: all issued before any dependent use ----
    const float2* q0 = (const float2*)&g_gramp[0][a * B];
    const float2* q1 = (const float2*)&g_gramp[1][a * B];
    const float2* q2 = (const float2*)&g_gramp[2][a * B];
    const float2* q3 = (const float2*)&g_gramp[3][a * B];
    float2 v0 = q0[tid];
    float2 v1 = q1[tid];
    float2 v2 = q2[tid];
    float2 v3 = q3[tid];
    float2 sq = ((const float2*)g_sqn)[tid];
    int2   tt = ((const int2*)types)[tid];
    int ta = types[a];          // uniform, L2-resident
    float sa = g_sqn[a];        // uniform

    int ja = 2 * tid, jb = 2 * tid + 1;
    float ga = v0.x + v1.x + v2.x + v3.x;
    float gb = v0.y + v1.y + v2.y + v3.y;
    float dva = (ja == a) ? 0.f : sqrtf(fmaxf(sa + sq.x - 2.f * ga, 0.f));
    float dvb = (jb == a) ? 0.f : sqrtf(fmaxf(sa + sq.y - 2.f * gb, 0.f));
    bool pa = (tt.x == ta);
    bool pb = (tt.y == ta);

    __syncthreads();  // cnt init visible

    unsigned lt_mask = (1u << lane) - 1u;
    // ---- compaction pass A (j even) ----
    {
        unsigned mp = __ballot_sync(0xffffffffu, pa);
        int cp = __popc(mp);
        int bp = 0, bn = 0;
        if (lane == 0) {
            bp = atomicAdd(&cnt[0], cp);
            bn = atomicAdd(&cnt[1], 32 - cp);
        }
        bp = __shfl_sync(0xffffffffu, bp, 0);
        bn = __shfl_sync(0xffffffffu, bn, 0);
        if (pa) posv[bp + __popc(mp & lt_mask)] = dva;
        else    negv[bn + __popc((~mp) & lt_mask)] = dva;
    }
    // ---- compaction pass B (j odd) ----
    {
        unsigned mp = __ballot_sync(0xffffffffu, pb);
        int cp = __popc(mp);
        int bp = 0, bn = 0;
        if (lane == 0) {
            bp = atomicAdd(&cnt[0], cp);
            bn = atomicAdd(&cnt[1], 32 - cp);
        }
        bp = __shfl_sync(0xffffffffu, bp, 0);
        bn = __shfl_sync(0xffffffffu, bn, 0);
        if (pb) posv[bp + __popc(mp & lt_mask)] = dvb;
        else    negv[bn + __popc((~mp) & lt_mask)] = dvb;
    }
    __syncthreads();

    int np = cnt[0], nn = cnt[1];
    int nn4 = (nn + 3) & ~3;
    int np4 = (np + 3) & ~3;
    if (tid < nn4 - nn) negv[nn + tid] = 1e30f;   // pad: max(dp - INF, 0) = 0
    if (tid < np4 - np) posv[np + tid] = -1e30f;  // pad: max(-INF - dn, 0) = 0
    __syncthreads();

    const float4* negv4 = (const float4*)negv;
    int nq = nn4 >> 2;
    float a0 = 0.f, a1 = 0.f, a2 = 0.f, a3 = 0.f;
    for (int p = warp * 4; p < np4; p += 32) {  // 8 warps x 4 positives each
        float dp0 = posv[p + 0] + MARGIN;
        float dp1 = posv[p + 1] + MARGIN;
        float dp2 = posv[p + 2] + MARGIN;
        float dp3 = posv[p + 3] + MARGIN;
        for (int n = lane; n < nq; n += 32) {
            float4 v = negv4[n];
            a0 += fmaxf(dp0 - v.x, 0.f); a0 += fmaxf(dp0 - v.y, 0.f);
            a0 += fmaxf(dp0 - v.z, 0.f); a0 += fmaxf(dp0 - v.w, 0.f);
            a1 += fmaxf(dp1 - v.x, 0.f); a1 += fmaxf(dp1 - v.y, 0.f);
            a1 += fmaxf(dp1 - v.z, 0.f); a1 += fmaxf(dp1 - v.w, 0.f);
            a2 += fmaxf(dp2 - v.x, 0.f); a2 += fmaxf(dp2 - v.y, 0.f);
            a2 += fmaxf(dp2 - v.z, 0.f); a2 += fmaxf(dp2 - v.w, 0.f);
            a3 += fmaxf(dp3 - v.x, 0.f); a3 += fmaxf(dp3 - v.y, 0.f);
            a3 += fmaxf(dp3 - v.w, 0.f); a3 += fmaxf(dp3 - v.z, 0.f);
        }
    }
    float acc = (a0 + a1) + (a2 + a3);

    #pragma unroll
    for (int o = 16; o; o >>= 1) acc += __shfl_down_sync(0xffffffffu, acc, o);
    if (lane == 0) ws[warp] = acc;
    __syncthreads();
    if (tid == 0) {
        float s = 0.f;
        #pragma unroll
        for (int w = 0; w < 8; w++) s += ws[w];
        atomicAdd(&g_sum, (double)s);
        atomicAdd(&g_count, (unsigned long long)((long long)np * nn));
        __threadfence();
        unsigned d = atomicInc(&g_done, 0xffffffffu);
        if (d == B - 1) {
            double S = atomicAdd(&g_sum, 0.0);
            unsigned long long C = atomicAdd(&g_count, 0ull);
            double V = (double)C;
            double b3 = 134217728.0;  // 512^3
            out[0] = (float)(((b3 - V) * (double)MARGIN + S) / V);
        }
    }
}

extern "C" void kernel_launch(void* const* d_in, const int* in_sizes, int n_in,
                              void* d_out, int out_size) {
    int ti = 0, ei = 1;
    if (in_sizes[0] == B * D) { ti = 1; ei = 0; }
    const int* types = (const int*)d_in[ti];
    const float* X = (const float*)d_in[ei];
    float* out = (float*)d_out;

    gram_sqnorm_kernel<<<148, 256>>>(X);
    triplet_kernel<<<B, 256>>>(types, out);
}